// round 7
// baseline (speedup 1.0000x reference)
#include <cuda_runtime.h>
#include <cuda_bf16.h>
#include <cstdint>

#define HDIM   256
#define NSUB   32768
#define NGLOB  65536
#define SSEG   1024
#define ESUB_MAX   262144
#define EGLOB_MAX  1048576
#define CAPS (ESUB_MAX  + 4 * NSUB)
#define CAPG (EGLOB_MAX + 4 * NGLOB)

// ---------------- scratch ----------------
__device__ float g_dis_sub[NSUB];
__device__ float g_dis_glob[NGLOB];
__device__ float g_pooled[SSEG * HDIM];
__device__ float g_cnt[SSEG];
__device__ float g_p2[SSEG * HDIM];
__device__ float g_gemb_part[64 * HDIM];
__device__ int   g_gcnt;

__device__ int g_cntdeg_sub[NSUB];
__device__ int g_cntdeg_glob[NGLOB];
__device__ int g_off_sub[NSUB + 1];
__device__ int g_off_glob[NGLOB + 1];
__device__ int g_cur_sub[NSUB];
__device__ int g_cur_glob[NGLOB];
__device__ int g_bsum_sub[NSUB / 256];
__device__ int g_bsum_glob[NGLOB / 256];
__device__ __align__(16) int g_csr_sub[CAPS];
__device__ __align__(16) int g_csr_glob[CAPG];

// delta machinery
__device__ int  g_inj[NGLOB];      // node injected?
__device__ int  g_slot[NGLOB];     // node -> subgraph slot
__device__ int  g_aff[NGLOB];      // node affected by inject?
__device__ int  g_ndelta;
__device__ __align__(8) int2 g_delta[EGLOB_MAX];
__device__ float g_aggb[NGLOB * HDIM];   // fp32 agg for affected nodes

__device__ __align__(16) __nv_bfloat16 g_hs_sub [(NSUB  + 1) * HDIM];
__device__ __align__(16) __nv_bfloat16 g_hs_glob[(NGLOB + 1) * HDIM];
__device__ __align__(16) __nv_bfloat16 g_bA_sub [NSUB  * HDIM];
__device__ __align__(16) __nv_bfloat16 g_bA_glob[NGLOB * HDIM];
__device__ __align__(16) __nv_bfloat16 g_bA_pool[SSEG  * HDIM];
__device__ __align__(16) __nv_bfloat16 g_bWt_sub [HDIM * HDIM];
__device__ __align__(16) __nv_bfloat16 g_bWt_glob[HDIM * HDIM];

// ---------------- PTX helpers ----------------
__device__ __forceinline__ void red4(float* p, float x, float y, float z, float w) {
    asm volatile("red.global.add.v4.f32 [%0], {%1, %2, %3, %4};"
                 :: "l"(p), "f"(x), "f"(y), "f"(z), "f"(w) : "memory");
}
__device__ __forceinline__ void cp_async16(uint32_t dst, const void* src) {
    asm volatile("cp.async.cg.shared.global [%0], [%1], 16;" :: "r"(dst), "l"(src) : "memory");
}
__device__ __forceinline__ void cp_commit() {
    asm volatile("cp.async.commit_group;" ::: "memory");
}
template <int N>
__device__ __forceinline__ void cp_wait() {
    asm volatile("cp.async.wait_group %0;" :: "n"(N) : "memory");
}
__device__ __forceinline__ void ldsm_x4(uint32_t& r0, uint32_t& r1, uint32_t& r2, uint32_t& r3,
                                        uint32_t addr) {
    asm volatile("ldmatrix.sync.aligned.m8n8.x4.shared.b16 {%0,%1,%2,%3}, [%4];"
                 : "=r"(r0), "=r"(r1), "=r"(r2), "=r"(r3) : "r"(addr));
}
__device__ __forceinline__ void mma_bf16(float* c, const uint32_t* a, const uint32_t* b) {
    asm volatile(
        "mma.sync.aligned.m16n8k16.row.col.f32.bf16.bf16.f32 "
        "{%0,%1,%2,%3}, {%4,%5,%6,%7}, {%8,%9}, {%0,%1,%2,%3};"
        : "+f"(c[0]), "+f"(c[1]), "+f"(c[2]), "+f"(c[3])
        : "r"(a[0]), "r"(a[1]), "r"(a[2]), "r"(a[3]), "r"(b[0]), "r"(b[1]));
}
__device__ __forceinline__ __nv_bfloat162 badd2(__nv_bfloat162 a, __nv_bfloat162 b) {
    return __hadd2(a, b);
}

// ---------------- init ----------------
__global__ void k_zero_cnt() {
    int i = blockIdx.x * blockDim.x + threadIdx.x;   // grid covers NGLOB
    if (i < NGLOB) {
        g_cntdeg_glob[i] = 0;
        g_inj[i] = 0;
        g_aff[i] = 0;
    }
    if (i < NSUB)  g_cntdeg_sub[i]  = 0;
    if (i < HDIM) {
        g_hs_sub [NSUB  * HDIM + i] = __float2bfloat16(0.0f);
        g_hs_glob[NGLOB * HDIM + i] = __float2bfloat16(0.0f);
    }
    if (i == 0) { g_gcnt = 0; g_ndelta = 0; }
}
__global__ void k_zero_rest() {
    int i = blockIdx.x * blockDim.x + threadIdx.x;   // grid covers SSEG*HDIM
    if (i < SSEG * HDIM) g_pooled[i] = 0.0f;
    if (i < 64 * HDIM)   g_gemb_part[i] = 0.0f;
    if (i < SSEG)        g_cnt[i] = 0.0f;
}
__global__ void k_mark(const int* __restrict__ sub_index) {
    int s = blockIdx.x * blockDim.x + threadIdx.x;
    if (s >= SSEG) return;
    int node = sub_index[s];
    g_inj[node]  = 1;
    g_aff[node]  = 1;
    g_slot[node] = s;
}
__global__ void k_hist(int* __restrict__ cnt, const int* __restrict__ ei, int E) {
    int i = blockIdx.x * blockDim.x + threadIdx.x;
    if (i < E) atomicAdd(&cnt[ei[E + i]], 1);
}

// ---- parallel padded-degree scan ----
__global__ void k_scan1(const int* __restrict__ cnt, float* __restrict__ dis,
                        int* __restrict__ bsum) {
    __shared__ int sh[8];
    int i = blockIdx.x * 256 + threadIdx.x;
    int c = cnt[i];
    dis[i] = rsqrtf((float)c + 1.0f);
    int p = (c + 3) & ~3;
    for (int o = 16; o; o >>= 1) p += __shfl_down_sync(~0u, p, o);
    if ((threadIdx.x & 31) == 0) sh[threadIdx.x >> 5] = p;
    __syncthreads();
    if (threadIdx.x < 8) {
        int v = sh[threadIdx.x];
        for (int o = 4; o; o >>= 1) v += __shfl_down_sync(0xff, v, o);
        if (threadIdx.x == 0) bsum[blockIdx.x] = v;
    }
}
__global__ void k_scan2(int* __restrict__ bsum, int NB) {
    __shared__ int sh[256];
    int t = threadIdx.x;
    int v = (t < NB) ? bsum[t] : 0;
    sh[t] = v;
    __syncthreads();
    for (int d = 1; d < 256; d <<= 1) {
        int u = (t >= d) ? sh[t - d] : 0;
        __syncthreads();
        sh[t] += u;
        __syncthreads();
    }
    if (t < NB) bsum[t] = sh[t] - v;
}
__global__ void k_scan3(const int* __restrict__ cnt, const int* __restrict__ bsum,
                        int* __restrict__ off, int* __restrict__ cur, int N) {
    __shared__ int sh[256];
    int t = threadIdx.x;
    int i = blockIdx.x * 256 + t;
    int c = cnt[i];
    int p = (c + 3) & ~3;
    sh[t] = p;
    __syncthreads();
    for (int d = 1; d < 256; d <<= 1) {
        int u = (t >= d) ? sh[t - d] : 0;
        __syncthreads();
        sh[t] += u;
        __syncthreads();
    }
    int excl = sh[t] - p + bsum[blockIdx.x];
    off[i] = excl;
    cur[i] = excl;
    if (i == N - 1) off[N] = excl + p;
}
// plain fill (sub graph)
__global__ void k_fill(int* __restrict__ csr, int* __restrict__ cur,
                       const int* __restrict__ ei, int E) {
    int i = blockIdx.x * blockDim.x + threadIdx.x;
    if (i >= E) return;
    int p = atomicAdd(&cur[ei[E + i]], 1);
    csr[p] = ei[i];
}
// glob fill: also record delta edges from injected sources + mark affected dsts
__global__ void k_fill_glob(int* __restrict__ csr, int* __restrict__ cur,
                            const int* __restrict__ ei, int E) {
    int i = blockIdx.x * blockDim.x + threadIdx.x;
    if (i >= E) return;
    int src = ei[i], dst = ei[E + i];
    int p = atomicAdd(&cur[dst], 1);
    csr[p] = src;
    if (g_inj[src]) {
        int d = atomicAdd(&g_ndelta, 1);
        g_delta[d] = make_int2(src, dst);
        g_aff[dst] = 1;
    }
}
__global__ void k_pad(const int* __restrict__ cnt, const int* __restrict__ off,
                      int* __restrict__ csr, int N) {
    int i = blockIdx.x * blockDim.x + threadIdx.x;
    if (i >= N) return;
    int c = cnt[i], o = off[i], p = (c + 3) & ~3;
    for (int j = c; j < p; j++) csr[o + j] = N;
}

// ---------------- packs ----------------
__global__ void k_pack_A(const float* __restrict__ A, __nv_bfloat16* __restrict__ out, int M) {
    int vid = blockIdx.x * blockDim.x + threadIdx.x;
    if (vid >= M * 64) return;
    float4 v = ((const float4*)A)[vid];
    __nv_bfloat162 lo = __floats2bfloat162_rn(v.x, v.y);
    __nv_bfloat162 hi = __floats2bfloat162_rn(v.z, v.w);
    ((uint2*)out)[vid] = make_uint2(*reinterpret_cast<uint32_t*>(&lo),
                                    *reinterpret_cast<uint32_t*>(&hi));
}
__global__ void k_pack_Wt(const float* __restrict__ W, __nv_bfloat16* __restrict__ out) {
    __shared__ float tile[32][33];
    int bx = blockIdx.x * 32, by = blockIdx.y * 32;
    int tx = threadIdx.x & 31, ty = threadIdx.x >> 5;
    for (int i = 0; i < 32; i += 8)
        tile[ty + i][tx] = W[(by + ty + i) * HDIM + bx + tx];
    __syncthreads();
    for (int i = 0; i < 32; i += 8)
        out[(bx + ty + i) * HDIM + by + tx] = __float2bfloat16(tile[tx][ty + i]);
}

// ---------------- bf16 mma GEMM ----------------
#define GEMM_SMEM (4 * 16384)
__global__ __launch_bounds__(256, 2) void k_gemm_mma(
    const __nv_bfloat16* __restrict__ A,
    const __nv_bfloat16* __restrict__ Wt,
    __nv_bfloat16* __restrict__ Hs,
    float* __restrict__ Cf,
    const float* __restrict__ dis)
{
    extern __shared__ __align__(16) unsigned char smem[];
    const int tid  = threadIdx.x;
    const int lane = tid & 31, warp = tid >> 5;
    const int wm = warp & 3, wn = warp >> 2;
    const int row0 = blockIdx.x * 128, col0 = blockIdx.y * 128;
    uint32_t sbase = (uint32_t)__cvta_generic_to_shared(smem);

    float acc[2][8][4];
#pragma unroll
    for (int mt = 0; mt < 2; mt++)
#pragma unroll
        for (int nt = 0; nt < 8; nt++)
#pragma unroll
            for (int i = 0; i < 4; i++) acc[mt][nt][i] = 0.0f;

    auto load_stage = [&](int s, int kc) {
        const __nv_bfloat16* Ag = A  + (size_t)(row0)*HDIM + kc * 64;
        const __nv_bfloat16* Bg = Wt + (size_t)(col0)*HDIM + kc * 64;
        uint32_t sA = sbase + s * 16384;
        uint32_t sB = sbase + 32768 + s * 16384;
#pragma unroll
        for (int i = 0; i < 4; i++) {
            int id = tid + i * 256;
            int r = id >> 3, c = id & 7;
            uint32_t d = (uint32_t)(r * 128 + ((c ^ (r & 7)) << 4));
            cp_async16(sA + d, Ag + (size_t)r * HDIM + c * 8);
            cp_async16(sB + d, Bg + (size_t)r * HDIM + c * 8);
        }
        cp_commit();
    };

    load_stage(0, 0);
    int s = 0;
#pragma unroll 1
    for (int kc = 0; kc < 4; kc++) {
        if (kc < 3) load_stage(s ^ 1, kc + 1);
        if (kc < 3) cp_wait<1>(); else cp_wait<0>();
        __syncthreads();
        uint32_t sA = sbase + s * 16384;
        uint32_t sB = sbase + 32768 + s * 16384;
#pragma unroll
        for (int kk = 0; kk < 4; kk++) {
            uint32_t af[2][4];
#pragma unroll
            for (int mt = 0; mt < 2; mt++) {
                int r = wm * 32 + mt * 16 + (lane & 15);
                int c = kk * 2 + (lane >> 4);
                ldsm_x4(af[mt][0], af[mt][1], af[mt][2], af[mt][3],
                        sA + r * 128 + ((c ^ (r & 7)) << 4));
            }
            uint32_t bf[8][2];
#pragma unroll
            for (int p = 0; p < 4; p++) {
                int r = wn * 64 + p * 16 + ((lane >> 4) << 3) + (lane & 7);
                int c = kk * 2 + ((lane >> 3) & 1);
                ldsm_x4(bf[2 * p][0], bf[2 * p][1], bf[2 * p + 1][0], bf[2 * p + 1][1],
                        sB + r * 128 + ((c ^ (r & 7)) << 4));
            }
#pragma unroll
            for (int mt = 0; mt < 2; mt++)
#pragma unroll
                for (int nt = 0; nt < 8; nt++)
                    mma_bf16(acc[mt][nt], af[mt], bf[nt]);
        }
        __syncthreads();
        s ^= 1;
    }

    const int g = lane >> 2, t4 = lane & 3;
#pragma unroll
    for (int mt = 0; mt < 2; mt++) {
        int r_lo = row0 + wm * 32 + mt * 16 + g;
        int r_hi = r_lo + 8;
        if (dis) {
            float dlo = dis[r_lo], dhi = dis[r_hi];
#pragma unroll
            for (int nt = 0; nt < 8; nt++) {
                int col = col0 + wn * 64 + nt * 8 + 2 * t4;
                __nv_bfloat162 lo = __floats2bfloat162_rn(acc[mt][nt][0] * dlo,
                                                          acc[mt][nt][1] * dlo);
                __nv_bfloat162 hi = __floats2bfloat162_rn(acc[mt][nt][2] * dhi,
                                                          acc[mt][nt][3] * dhi);
                *(__nv_bfloat162*)&Hs[(size_t)r_lo * HDIM + col] = lo;
                *(__nv_bfloat162*)&Hs[(size_t)r_hi * HDIM + col] = hi;
            }
        } else {
#pragma unroll
            for (int nt = 0; nt < 8; nt++) {
                int col = col0 + wn * 64 + nt * 8 + 2 * t4;
                *(float2*)&Cf[(size_t)r_lo * HDIM + col] =
                    make_float2(acc[mt][nt][0], acc[mt][nt][1]);
                *(float2*)&Cf[(size_t)r_hi * HDIM + col] =
                    make_float2(acc[mt][nt][2], acc[mt][nt][3]);
            }
        }
    }
}

// ---------------- CSR gather + fused epilogues ----------------
__global__ __launch_bounds__(256) void k_gather_sub(
    const int* __restrict__ batch, const float* __restrict__ bias)
{
    const int lane = threadIdx.x & 31, grp = threadIdx.x >> 5;
    const uint4* H = (const uint4*)g_hs_sub;
    float4 b0 = ((const float4*)bias)[lane * 2];
    float4 b1 = ((const float4*)bias)[lane * 2 + 1];
#pragma unroll 1
    for (int it = 0; it < 4; it++) {
        int n = blockIdx.x * 32 + it * 8 + grp;
        int o0 = g_off_sub[n] >> 2, o1 = g_off_sub[n + 1] >> 2;
        uint4 a = H[(size_t)n * 32 + lane];
        __nv_bfloat162 A0 = *(__nv_bfloat162*)&a.x, A1 = *(__nv_bfloat162*)&a.y,
                       A2 = *(__nv_bfloat162*)&a.z, A3 = *(__nv_bfloat162*)&a.w;
#pragma unroll 1
        for (int k = o0; k < o1; k++) {
            int4 s4 = ((const int4*)g_csr_sub)[k];
            uint4 v;
            v = H[(size_t)s4.x * 32 + lane];
            A0 = badd2(A0, *(__nv_bfloat162*)&v.x); A1 = badd2(A1, *(__nv_bfloat162*)&v.y);
            A2 = badd2(A2, *(__nv_bfloat162*)&v.z); A3 = badd2(A3, *(__nv_bfloat162*)&v.w);
            v = H[(size_t)s4.y * 32 + lane];
            A0 = badd2(A0, *(__nv_bfloat162*)&v.x); A1 = badd2(A1, *(__nv_bfloat162*)&v.y);
            A2 = badd2(A2, *(__nv_bfloat162*)&v.z); A3 = badd2(A3, *(__nv_bfloat162*)&v.w);
            v = H[(size_t)s4.z * 32 + lane];
            A0 = badd2(A0, *(__nv_bfloat162*)&v.x); A1 = badd2(A1, *(__nv_bfloat162*)&v.y);
            A2 = badd2(A2, *(__nv_bfloat162*)&v.z); A3 = badd2(A3, *(__nv_bfloat162*)&v.w);
            v = H[(size_t)s4.w * 32 + lane];
            A0 = badd2(A0, *(__nv_bfloat162*)&v.x); A1 = badd2(A1, *(__nv_bfloat162*)&v.y);
            A2 = badd2(A2, *(__nv_bfloat162*)&v.z); A3 = badd2(A3, *(__nv_bfloat162*)&v.w);
        }
        float d = g_dis_sub[n];
        float2 f0 = __bfloat1622float2(A0), f1 = __bfloat1622float2(A1);
        float2 f2 = __bfloat1622float2(A2), f3 = __bfloat1622float2(A3);
        float* dst = g_pooled + (size_t)batch[n] * HDIM + lane * 8;
        red4(dst,
             fmaxf(fmaf(f0.x, d, b0.x), 0.0f), fmaxf(fmaf(f0.y, d, b0.y), 0.0f),
             fmaxf(fmaf(f1.x, d, b0.z), 0.0f), fmaxf(fmaf(f1.y, d, b0.w), 0.0f));
        red4(dst + 4,
             fmaxf(fmaf(f2.x, d, b1.x), 0.0f), fmaxf(fmaf(f2.y, d, b1.y), 0.0f),
             fmaxf(fmaf(f3.x, d, b1.z), 0.0f), fmaxf(fmaf(f3.y, d, b1.w), 0.0f));
    }
}

// glob base gather over PRE-inject hs: skip affected nodes in mean; stash their fp32 agg.
__global__ __launch_bounds__(256) void k_gather_glob_base(
    const int* __restrict__ batch, const float* __restrict__ bias)
{
    const int lane = threadIdx.x & 31, grp = threadIdx.x >> 5;
    const uint4* H = (const uint4*)g_hs_glob;
    float4 b0 = ((const float4*)bias)[lane * 2];
    float4 b1 = ((const float4*)bias)[lane * 2 + 1];
    float r0 = 0, r1 = 0, r2 = 0, r3 = 0, r4 = 0, r5 = 0, r6 = 0, r7 = 0;
    int cloc = 0;
#pragma unroll 1
    for (int it = 0; it < 4; it++) {
        int n = blockIdx.x * 32 + it * 8 + grp;
        int o0 = g_off_glob[n] >> 2, o1 = g_off_glob[n + 1] >> 2;
        uint4 a = H[(size_t)n * 32 + lane];
        __nv_bfloat162 A0 = *(__nv_bfloat162*)&a.x, A1 = *(__nv_bfloat162*)&a.y,
                       A2 = *(__nv_bfloat162*)&a.z, A3 = *(__nv_bfloat162*)&a.w;
#pragma unroll 1
        for (int k = o0; k < o1; k++) {
            int4 s4 = ((const int4*)g_csr_glob)[k];
            uint4 v;
            v = H[(size_t)s4.x * 32 + lane];
            A0 = badd2(A0, *(__nv_bfloat162*)&v.x); A1 = badd2(A1, *(__nv_bfloat162*)&v.y);
            A2 = badd2(A2, *(__nv_bfloat162*)&v.z); A3 = badd2(A3, *(__nv_bfloat162*)&v.w);
            v = H[(size_t)s4.y * 32 + lane];
            A0 = badd2(A0, *(__nv_bfloat162*)&v.x); A1 = badd2(A1, *(__nv_bfloat162*)&v.y);
            A2 = badd2(A2, *(__nv_bfloat162*)&v.z); A3 = badd2(A3, *(__nv_bfloat162*)&v.w);
            v = H[(size_t)s4.z * 32 + lane];
            A0 = badd2(A0, *(__nv_bfloat162*)&v.x); A1 = badd2(A1, *(__nv_bfloat162*)&v.y);
            A2 = badd2(A2, *(__nv_bfloat162*)&v.z); A3 = badd2(A3, *(__nv_bfloat162*)&v.w);
            v = H[(size_t)s4.w * 32 + lane];
            A0 = badd2(A0, *(__nv_bfloat162*)&v.x); A1 = badd2(A1, *(__nv_bfloat162*)&v.y);
            A2 = badd2(A2, *(__nv_bfloat162*)&v.z); A3 = badd2(A3, *(__nv_bfloat162*)&v.w);
        }
        int aff = g_aff[n];
        int b0n = (batch[n] == 0);
        float d = g_dis_glob[n];
        float2 f0 = __bfloat1622float2(A0), f1 = __bfloat1622float2(A1);
        float2 f2 = __bfloat1622float2(A2), f3 = __bfloat1622float2(A3);
        if (aff) {   // stash raw fp32 agg (dis-scaled, no bias/relu)
            float* ap = g_aggb + (size_t)n * HDIM + lane * 8;
            *(float4*)ap       = make_float4(f0.x * d, f0.y * d, f1.x * d, f1.y * d);
            *(float4*)(ap + 4) = make_float4(f2.x * d, f2.y * d, f3.x * d, f3.y * d);
        } else if (b0n) {
            r0 += fmaxf(fmaf(f0.x, d, b0.x), 0.0f);
            r1 += fmaxf(fmaf(f0.y, d, b0.y), 0.0f);
            r2 += fmaxf(fmaf(f1.x, d, b0.z), 0.0f);
            r3 += fmaxf(fmaf(f1.y, d, b0.w), 0.0f);
            r4 += fmaxf(fmaf(f2.x, d, b1.x), 0.0f);
            r5 += fmaxf(fmaf(f2.y, d, b1.y), 0.0f);
            r6 += fmaxf(fmaf(f3.x, d, b1.z), 0.0f);
            r7 += fmaxf(fmaf(f3.y, d, b1.w), 0.0f);
        }
        cloc += b0n;
    }
    float* dst = g_gemb_part + (size_t)(blockIdx.x & 63) * HDIM + lane * 8;
    red4(dst, r0, r1, r2, r3);
    red4(dst + 4, r4, r5, r6, r7);
    if (lane == 0) atomicAdd(&g_gcnt, cloc);
}

// ---------------- delta kernels ----------------
// self term: aggb[node] += dis[node]^2 * p2[s]
__global__ void k_delta_self(const int* __restrict__ sub_index) {
    int idx = blockIdx.x * blockDim.x + threadIdx.x;   // float4 units over SSEG*64
    if (idx >= SSEG * 64) return;
    int s = idx >> 6, c = idx & 63;
    int node = sub_index[s];
    float d = g_dis_glob[node];
    float d2 = d * d;
    float4 v = ((const float4*)g_p2)[(size_t)s * 64 + c];
    red4(g_aggb + (size_t)node * HDIM + c * 4, v.x * d2, v.y * d2, v.z * d2, v.w * d2);
}
// edge term: aggb[dst] += dis[dst]*dis[src]*p2[slot(src)]  (grid-stride, 64 lanes/edge)
__global__ void k_delta_edges() {
    int nd = g_ndelta;
    int lane = threadIdx.x & 63;
    for (int e = blockIdx.x * 4 + (threadIdx.x >> 6); e < nd; e += gridDim.x * 4) {
        int2 ed = g_delta[e];
        int s = g_slot[ed.x];
        float nm = g_dis_glob[ed.x] * g_dis_glob[ed.y];
        float4 v = ((const float4*)g_p2)[(size_t)s * 64 + lane];
        red4(g_aggb + (size_t)ed.y * HDIM + lane * 4, v.x * nm, v.y * nm, v.z * nm, v.w * nm);
    }
}
// fixup: add relu(agg_new + b) for affected batch==0 nodes
__global__ void k_fixup(const int* __restrict__ batch, const float* __restrict__ bias) {
    int lane = threadIdx.x & 31, grp = threadIdx.x >> 5;
    int n = blockIdx.x * 8 + grp;
    if (!g_aff[n] || batch[n] != 0) return;
    const float* ap = g_aggb + (size_t)n * HDIM + lane * 8;
    float4 a0 = *(const float4*)ap;
    float4 a1 = *(const float4*)(ap + 4);
    float4 b0 = ((const float4*)bias)[lane * 2];
    float4 b1 = ((const float4*)bias)[lane * 2 + 1];
    float* dst = g_gemb_part + (size_t)(blockIdx.x & 63) * HDIM + lane * 8;
    red4(dst,
         fmaxf(a0.x + b0.x, 0.0f), fmaxf(a0.y + b0.y, 0.0f),
         fmaxf(a0.z + b0.z, 0.0f), fmaxf(a0.w + b0.w, 0.0f));
    red4(dst + 4,
         fmaxf(a1.x + b1.x, 0.0f), fmaxf(a1.y + b1.y, 0.0f),
         fmaxf(a1.z + b1.z, 0.0f), fmaxf(a1.w + b1.w, 0.0f));
}

// ---------------- misc ----------------
__global__ void k_cnt_sub(const int* __restrict__ batch, int N) {
    int i = blockIdx.x * blockDim.x + threadIdx.x;
    if (i < N) atomicAdd(&g_cnt[batch[i]], 1.0f);
}
// fused pooled/cnt divide + bf16 pack
__global__ void k_pool_finish() {
    int vid = blockIdx.x * blockDim.x + threadIdx.x;   // float4 units over SSEG*64
    if (vid >= SSEG * 64) return;
    int s = vid >> 6;
    float inv = 1.0f / fmaxf(g_cnt[s], 1.0f);
    float4 v = ((const float4*)g_pooled)[vid];
    v.x *= inv; v.y *= inv; v.z *= inv; v.w *= inv;
    ((float4*)g_pooled)[vid] = v;   // fp32 pooled kept (not used later, cheap)
    __nv_bfloat162 lo = __floats2bfloat162_rn(v.x, v.y);
    __nv_bfloat162 hi = __floats2bfloat162_rn(v.z, v.w);
    ((uint2*)g_bA_pool)[vid] = make_uint2(*reinterpret_cast<uint32_t*>(&lo),
                                          *reinterpret_cast<uint32_t*>(&hi));
}
__global__ void k_final(const float* __restrict__ fc_W, const float* __restrict__ fc_b,
                        float* __restrict__ out) {
    __shared__ float sg[HDIM];
    int t = threadIdx.x;
    float s = 0.0f;
#pragma unroll 8
    for (int p = 0; p < 64; p++) s += g_gemb_part[p * HDIM + t];
    sg[t] = s / fmaxf((float)g_gcnt, 1.0f);
    __syncthreads();
    float acc = fc_b[t];
    const float* wr = fc_W + (size_t)t * HDIM;
#pragma unroll 8
    for (int h = 0; h < HDIM; h++) acc = fmaf(sg[h], wr[h], acc);
    out[t] = acc;
}

// ---------------- host launcher ----------------
extern "C" void kernel_launch(void* const* d_in, const int* in_sizes, int n_in,
                              void* d_out, int out_size) {
    const float* x_sub      = (const float*)d_in[0];
    const int*   ei_sub     = (const int*)  d_in[1];
    const int*   batch_sub  = (const int*)  d_in[2];
    const int*   sub_index  = (const int*)  d_in[3];
    const float* x_glob     = (const float*)d_in[4];
    const int*   ei_glob    = (const int*)  d_in[5];
    const int*   batch_glob = (const int*)  d_in[6];
    const float* W_sub      = (const float*)d_in[7];
    const float* b_sub      = (const float*)d_in[8];
    const float* W_glob     = (const float*)d_in[9];
    const float* b_glob     = (const float*)d_in[10];
    const float* fc_W       = (const float*)d_in[11];
    const float* fc_b       = (const float*)d_in[12];
    float* out = (float*)d_out;

    const int E_sub  = in_sizes[1] / 2;
    const int E_glob = in_sizes[5] / 2;

    static bool init = false;
    static float *p_dis_sub, *p_dis_glob, *p_pooled, *p_p2;
    static int *p_cd_sub, *p_cd_glob, *p_off_sub, *p_off_glob, *p_cur_sub, *p_cur_glob,
               *p_csr_sub, *p_csr_glob, *p_bs_sub, *p_bs_glob;
    static __nv_bfloat16 *pb_a_sub, *pb_a_glob, *pb_a_pool, *pb_wt_sub, *pb_wt_glob,
                         *p_hs_sub, *p_hs_glob;
    static cudaStream_t s2, s3, s4;
    static cudaEvent_t eStart, eZ, eZ2, eDs, eDg, ePWg, eCSRs, eCSRg, eGB;
    if (!init) {
        init = true;
        cudaGetSymbolAddress((void**)&p_dis_sub,  g_dis_sub);
        cudaGetSymbolAddress((void**)&p_dis_glob, g_dis_glob);
        cudaGetSymbolAddress((void**)&p_pooled,   g_pooled);
        cudaGetSymbolAddress((void**)&p_p2,       g_p2);
        cudaGetSymbolAddress((void**)&p_cd_sub,   g_cntdeg_sub);
        cudaGetSymbolAddress((void**)&p_cd_glob,  g_cntdeg_glob);
        cudaGetSymbolAddress((void**)&p_off_sub,  g_off_sub);
        cudaGetSymbolAddress((void**)&p_off_glob, g_off_glob);
        cudaGetSymbolAddress((void**)&p_cur_sub,  g_cur_sub);
        cudaGetSymbolAddress((void**)&p_cur_glob, g_cur_glob);
        cudaGetSymbolAddress((void**)&p_csr_sub,  g_csr_sub);
        cudaGetSymbolAddress((void**)&p_csr_glob, g_csr_glob);
        cudaGetSymbolAddress((void**)&p_bs_sub,   g_bsum_sub);
        cudaGetSymbolAddress((void**)&p_bs_glob,  g_bsum_glob);
        cudaGetSymbolAddress((void**)&pb_a_sub,   g_bA_sub);
        cudaGetSymbolAddress((void**)&pb_a_glob,  g_bA_glob);
        cudaGetSymbolAddress((void**)&pb_a_pool,  g_bA_pool);
        cudaGetSymbolAddress((void**)&pb_wt_sub,  g_bWt_sub);
        cudaGetSymbolAddress((void**)&pb_wt_glob, g_bWt_glob);
        cudaGetSymbolAddress((void**)&p_hs_sub,   g_hs_sub);
        cudaGetSymbolAddress((void**)&p_hs_glob,  g_hs_glob);
        cudaFuncSetAttribute(k_gemm_mma, cudaFuncAttributeMaxDynamicSharedMemorySize, GEMM_SMEM);
        cudaStreamCreateWithFlags(&s2, cudaStreamNonBlocking);
        cudaStreamCreateWithFlags(&s3, cudaStreamNonBlocking);
        cudaStreamCreateWithFlags(&s4, cudaStreamNonBlocking);
        cudaEventCreateWithFlags(&eStart, cudaEventDisableTiming);
        cudaEventCreateWithFlags(&eZ,     cudaEventDisableTiming);
        cudaEventCreateWithFlags(&eZ2,    cudaEventDisableTiming);
        cudaEventCreateWithFlags(&eDs,    cudaEventDisableTiming);
        cudaEventCreateWithFlags(&eDg,    cudaEventDisableTiming);
        cudaEventCreateWithFlags(&ePWg,   cudaEventDisableTiming);
        cudaEventCreateWithFlags(&eCSRs,  cudaEventDisableTiming);
        cudaEventCreateWithFlags(&eCSRg,  cudaEventDisableTiming);
        cudaEventCreateWithFlags(&eGB,    cudaEventDisableTiming);
    }

    // ---- fork ----
    cudaEventRecord(eStart, 0);
    cudaStreamWaitEvent(s2, eStart, 0);
    cudaStreamWaitEvent(s3, eStart, 0);
    cudaStreamWaitEvent(s4, eStart, 0);

    // s0: zeroing
    k_zero_cnt <<<NGLOB / 256, 256>>>();
    cudaEventRecord(eZ, 0);
    k_zero_rest<<<(SSEG * HDIM + 255) / 256, 256>>>();
    cudaEventRecord(eZ2, 0);

    // ---- s2: glob CSR build (+ mark + delta recording) ----
    cudaStreamWaitEvent(s2, eZ, 0);
    k_hist <<<(E_glob + 255) / 256, 256, 0, s2>>>(p_cd_glob, ei_glob, E_glob);
    k_scan1<<<NGLOB / 256, 256, 0, s2>>>(p_cd_glob, p_dis_glob, p_bs_glob);
    cudaEventRecord(eDg, s2);
    k_scan2<<<1, 256, 0, s2>>>(p_bs_glob, NGLOB / 256);
    k_scan3<<<NGLOB / 256, 256, 0, s2>>>(p_cd_glob, p_bs_glob, p_off_glob, p_cur_glob, NGLOB);
    k_mark <<<SSEG / 256, 256, 0, s2>>>(sub_index);
    k_fill_glob<<<(E_glob + 255) / 256, 256, 0, s2>>>(p_csr_glob, p_cur_glob, ei_glob, E_glob);
    k_pad  <<<NGLOB / 256, 256, 0, s2>>>(p_cd_glob, p_off_glob, p_csr_glob, NGLOB);
    cudaEventRecord(eCSRg, s2);

    // ---- s3: glob pack + GEMM + base gather (off the join tail!) ----
    k_pack_Wt<<<dim3(8, 8), 256, 0, s3>>>(W_glob, pb_wt_glob);
    cudaEventRecord(ePWg, s3);
    k_pack_A <<<(NGLOB * 64 + 255) / 256, 256, 0, s3>>>(x_glob, pb_a_glob, NGLOB);
    cudaStreamWaitEvent(s3, eDg, 0);
    k_gemm_mma<<<dim3(NGLOB / 128, 2), 256, GEMM_SMEM, s3>>>(pb_a_glob, pb_wt_glob,
                                                             p_hs_glob, nullptr, p_dis_glob);
    cudaStreamWaitEvent(s3, eCSRg, 0);
    cudaStreamWaitEvent(s3, eZ2, 0);
    k_gather_glob_base<<<NGLOB / 32, 256, 0, s3>>>(batch_glob, b_glob);
    cudaEventRecord(eGB, s3);

    // ---- s4: sub CSR build ----
    cudaStreamWaitEvent(s4, eZ, 0);
    k_hist <<<(E_sub + 255) / 256, 256, 0, s4>>>(p_cd_sub, ei_sub, E_sub);
    k_scan1<<<NSUB / 256, 256, 0, s4>>>(p_cd_sub, p_dis_sub, p_bs_sub);
    cudaEventRecord(eDs, s4);
    k_scan2<<<1, 256, 0, s4>>>(p_bs_sub, NSUB / 256);
    k_scan3<<<NSUB / 256, 256, 0, s4>>>(p_cd_sub, p_bs_sub, p_off_sub, p_cur_sub, NSUB);
    k_fill <<<(E_sub + 255) / 256, 256, 0, s4>>>(p_csr_sub, p_cur_sub, ei_sub, E_sub);
    k_pad  <<<NSUB / 256, 256, 0, s4>>>(p_cd_sub, p_off_sub, p_csr_sub, NSUB);
    cudaEventRecord(eCSRs, s4);

    // ---- s0: sub pack/GEMM/gather + pooled GEMM + delta tail ----
    k_pack_Wt<<<dim3(8, 8), 256>>>(W_sub, pb_wt_sub);
    k_pack_A <<<(NSUB * 64 + 255) / 256, 256>>>(x_sub, pb_a_sub, NSUB);
    k_cnt_sub<<<(NSUB + 255) / 256, 256>>>(batch_sub, NSUB);
    cudaStreamWaitEvent(0, eDs, 0);
    k_gemm_mma<<<dim3(NSUB / 128, 2), 256, GEMM_SMEM>>>(pb_a_sub, pb_wt_sub,
                                                        p_hs_sub, nullptr, p_dis_sub);
    cudaStreamWaitEvent(0, eCSRs, 0);
    k_gather_sub<<<NSUB / 32, 256>>>(batch_sub, b_sub);
    k_pool_finish<<<(SSEG * 64 + 255) / 256, 256>>>();
    cudaStreamWaitEvent(0, ePWg, 0);
    k_gemm_mma<<<dim3(SSEG / 128, 2), 256, GEMM_SMEM>>>(pb_a_pool, pb_wt_glob,
                                                        nullptr, p_p2, nullptr);

    // delta tail: needs base gather (aggb) + delta list
    cudaStreamWaitEvent(0, eGB, 0);
    cudaStreamWaitEvent(0, eCSRg, 0);
    k_delta_self <<<(SSEG * 64 + 255) / 256, 256>>>(sub_index);
    k_delta_edges<<<512, 256>>>();
    k_fixup<<<NGLOB / 8, 256>>>(batch_glob, b_glob);
    k_final<<<1, 256>>>(fc_W, fc_b, out);
}

// round 8
// speedup vs baseline: 1.0974x; 1.0974x over previous
#include <cuda_runtime.h>
#include <cuda_bf16.h>
#include <cstdint>

#define HDIM   256
#define NSUB   32768
#define NGLOB  65536
#define SSEG   1024
#define ESUB_MAX   262144
#define EGLOB_MAX  1048576
#define CAPS (ESUB_MAX  + 4 * NSUB)
#define CAPG (EGLOB_MAX + 4 * NGLOB)

// ---------------- scratch ----------------
__device__ float g_dis_sub[NSUB];
__device__ float g_dis_glob[NGLOB];
__device__ float g_pooled[SSEG * HDIM];
__device__ float g_cnt[SSEG];
__device__ float g_p2[SSEG * HDIM];
__device__ float g_gemb_part[64 * HDIM];
__device__ int   g_gcnt;

__device__ int g_cntdeg_sub[NSUB];
__device__ int g_cntdeg_glob[NGLOB];
__device__ int g_off_sub[NSUB + 1];
__device__ int g_off_glob[NGLOB + 1];
__device__ int g_cur_sub[NSUB];
__device__ int g_cur_glob[NGLOB];
__device__ int g_bsum_sub[NSUB / 256];
__device__ int g_bsum_glob[NGLOB / 256];
__device__ __align__(16) int g_csr_sub[CAPS];
__device__ __align__(16) int g_csr_glob[CAPG];

__device__ __align__(16) __nv_bfloat16 g_hs_sub [(NSUB  + 1) * HDIM];
__device__ __align__(16) __nv_bfloat16 g_hs_glob[(NGLOB + 1) * HDIM];
__device__ __align__(16) __nv_bfloat16 g_bWt_sub [HDIM * HDIM];
__device__ __align__(16) __nv_bfloat16 g_bWt_glob[HDIM * HDIM];

// ---------------- PTX helpers ----------------
__device__ __forceinline__ void red4(float* p, float x, float y, float z, float w) {
    asm volatile("red.global.add.v4.f32 [%0], {%1, %2, %3, %4};"
                 :: "l"(p), "f"(x), "f"(y), "f"(z), "f"(w) : "memory");
}
__device__ __forceinline__ void cp_async16(uint32_t dst, const void* src) {
    asm volatile("cp.async.cg.shared.global [%0], [%1], 16;" :: "r"(dst), "l"(src) : "memory");
}
__device__ __forceinline__ void cp_commit() {
    asm volatile("cp.async.commit_group;" ::: "memory");
}
template <int N>
__device__ __forceinline__ void cp_wait() {
    asm volatile("cp.async.wait_group %0;" :: "n"(N) : "memory");
}
__device__ __forceinline__ void ldsm_x4(uint32_t& r0, uint32_t& r1, uint32_t& r2, uint32_t& r3,
                                        uint32_t addr) {
    asm volatile("ldmatrix.sync.aligned.m8n8.x4.shared.b16 {%0,%1,%2,%3}, [%4];"
                 : "=r"(r0), "=r"(r1), "=r"(r2), "=r"(r3) : "r"(addr));
}
__device__ __forceinline__ void mma_bf16(float* c, const uint32_t* a, const uint32_t* b) {
    asm volatile(
        "mma.sync.aligned.m16n8k16.row.col.f32.bf16.bf16.f32 "
        "{%0,%1,%2,%3}, {%4,%5,%6,%7}, {%8,%9}, {%0,%1,%2,%3};"
        : "+f"(c[0]), "+f"(c[1]), "+f"(c[2]), "+f"(c[3])
        : "r"(a[0]), "r"(a[1]), "r"(a[2]), "r"(a[3]), "r"(b[0]), "r"(b[1]));
}
__device__ __forceinline__ __nv_bfloat162 badd2(__nv_bfloat162 a, __nv_bfloat162 b) {
    return __hadd2(a, b);
}

// ---------------- init ----------------
__global__ void k_zero_cnt() {
    int i = blockIdx.x * blockDim.x + threadIdx.x;   // grid covers NGLOB
    if (i < NGLOB) g_cntdeg_glob[i] = 0;
    if (i < NSUB)  g_cntdeg_sub[i]  = 0;
    if (i < HDIM) {
        g_hs_sub [NSUB  * HDIM + i] = __float2bfloat16(0.0f);
        g_hs_glob[NGLOB * HDIM + i] = __float2bfloat16(0.0f);
    }
    if (i == 0) g_gcnt = 0;
}
__global__ void k_zero_rest() {
    int i = blockIdx.x * blockDim.x + threadIdx.x;   // grid covers SSEG*HDIM
    if (i < SSEG * HDIM) g_pooled[i] = 0.0f;
    if (i < 64 * HDIM)   g_gemb_part[i] = 0.0f;
    if (i < SSEG)        g_cnt[i] = 0.0f;
}
__global__ void k_hist(int* __restrict__ cnt, const int* __restrict__ ei, int E) {
    int i = blockIdx.x * blockDim.x + threadIdx.x;
    if (i < E) atomicAdd(&cnt[ei[E + i]], 1);
}

// ---- parallel padded-degree scan ----
__global__ void k_scan1(const int* __restrict__ cnt, float* __restrict__ dis,
                        int* __restrict__ bsum) {
    __shared__ int sh[8];
    int i = blockIdx.x * 256 + threadIdx.x;
    int c = cnt[i];
    dis[i] = rsqrtf((float)c + 1.0f);
    int p = (c + 3) & ~3;
    for (int o = 16; o; o >>= 1) p += __shfl_down_sync(~0u, p, o);
    if ((threadIdx.x & 31) == 0) sh[threadIdx.x >> 5] = p;
    __syncthreads();
    if (threadIdx.x < 8) {
        int v = sh[threadIdx.x];
        for (int o = 4; o; o >>= 1) v += __shfl_down_sync(0xff, v, o);
        if (threadIdx.x == 0) bsum[blockIdx.x] = v;
    }
}
__global__ void k_scan2(int* __restrict__ bsum, int NB) {
    __shared__ int sh[256];
    int t = threadIdx.x;
    int v = (t < NB) ? bsum[t] : 0;
    sh[t] = v;
    __syncthreads();
    for (int d = 1; d < 256; d <<= 1) {
        int u = (t >= d) ? sh[t - d] : 0;
        __syncthreads();
        sh[t] += u;
        __syncthreads();
    }
    if (t < NB) bsum[t] = sh[t] - v;
}
__global__ void k_scan3(const int* __restrict__ cnt, const int* __restrict__ bsum,
                        int* __restrict__ off, int* __restrict__ cur, int N) {
    __shared__ int sh[256];
    int t = threadIdx.x;
    int i = blockIdx.x * 256 + t;
    int c = cnt[i];
    int p = (c + 3) & ~3;
    sh[t] = p;
    __syncthreads();
    for (int d = 1; d < 256; d <<= 1) {
        int u = (t >= d) ? sh[t - d] : 0;
        __syncthreads();
        sh[t] += u;
        __syncthreads();
    }
    int excl = sh[t] - p + bsum[blockIdx.x];
    off[i] = excl;
    cur[i] = excl;
    if (i == N - 1) off[N] = excl + p;
}
__global__ void k_fill(int* __restrict__ csr, int* __restrict__ cur,
                       const int* __restrict__ ei, int E) {
    int i = blockIdx.x * blockDim.x + threadIdx.x;
    if (i >= E) return;
    int p = atomicAdd(&cur[ei[E + i]], 1);
    csr[p] = ei[i];
}
__global__ void k_pad(const int* __restrict__ cnt, const int* __restrict__ off,
                      int* __restrict__ csr, int N) {
    int i = blockIdx.x * blockDim.x + threadIdx.x;
    if (i >= N) return;
    int c = cnt[i], o = off[i], p = (c + 3) & ~3;
    for (int j = c; j < p; j++) csr[o + j] = N;
}

// ---------------- W pack ----------------
__global__ void k_pack_Wt(const float* __restrict__ W, __nv_bfloat16* __restrict__ out) {
    __shared__ float tile[32][33];
    int bx = blockIdx.x * 32, by = blockIdx.y * 32;
    int tx = threadIdx.x & 31, ty = threadIdx.x >> 5;
    for (int i = 0; i < 32; i += 8)
        tile[ty + i][tx] = W[(by + ty + i) * HDIM + bx + tx];
    __syncthreads();
    for (int i = 0; i < 32; i += 8)
        out[(bx + ty + i) * HDIM + by + tx] = __float2bfloat16(tile[tx][ty + i]);
}

// ---------------- bf16 mma GEMM with in-kernel fp32->bf16 A conversion ----------------
// smem: [0,32768) fp32 A staging; [32768,+16K x2) bf16 A stages; [65536,+16K x2) B stages.
#define GEMM_SMEM (32768 + 32768 + 32768)
__global__ __launch_bounds__(256, 2) void k_gemm_mma(
    const float* __restrict__ A,          // fp32 [M,256]
    const __nv_bfloat16* __restrict__ Wt, // bf16 [256,256] (n-major)
    __nv_bfloat16* __restrict__ Hs,
    float* __restrict__ Cf,
    const float* __restrict__ dis)
{
    extern __shared__ __align__(16) unsigned char smem[];
    const int tid  = threadIdx.x;
    const int lane = tid & 31, warp = tid >> 5;
    const int wm = warp & 3, wn = warp >> 2;
    const int row0 = blockIdx.x * 128, col0 = blockIdx.y * 128;
    uint32_t sbase = (uint32_t)__cvta_generic_to_shared(smem);
    const uint32_t STG = sbase;
    const uint32_t ABF = sbase + 32768;
    const uint32_t BB  = sbase + 65536;

    float acc[2][8][4];
#pragma unroll
    for (int mt = 0; mt < 2; mt++)
#pragma unroll
        for (int nt = 0; nt < 8; nt++)
#pragma unroll
            for (int i = 0; i < 4; i++) acc[mt][nt][i] = 0.0f;

    auto load_A_stage = [&](int kc) {   // fp32 tile -> linear staging
#pragma unroll
        for (int i = 0; i < 8; i++) {
            int id = tid + i * 256;            // chunk of 4 floats
            int r = id >> 4, c4 = id & 15;
            cp_async16(STG + (uint32_t)id * 16,
                       A + (size_t)(row0 + r) * HDIM + kc * 64 + c4 * 4);
        }
    };
    auto load_B = [&](int s, int kc) {
#pragma unroll
        for (int i = 0; i < 4; i++) {
            int id = tid + i * 256;
            int r = id >> 3, c = id & 7;
            cp_async16(BB + s * 16384 + (uint32_t)(r * 128 + ((c ^ (r & 7)) << 4)),
                       Wt + (size_t)(col0 + r) * HDIM + kc * 64 + c * 8);
        }
    };
    auto convert_A = [&](int s) {       // staging fp32 -> swizzled bf16
#pragma unroll
        for (int i = 0; i < 8; i++) {
            int id = tid + i * 256;
            int r = id >> 4, c4 = id & 15;
            float4 v;
            asm volatile("ld.shared.v4.f32 {%0,%1,%2,%3}, [%4];"
                         : "=f"(v.x), "=f"(v.y), "=f"(v.z), "=f"(v.w)
                         : "r"(STG + (uint32_t)id * 16));
            __nv_bfloat162 lo = __floats2bfloat162_rn(v.x, v.y);
            __nv_bfloat162 hi = __floats2bfloat162_rn(v.z, v.w);
            int cc = c4 >> 1, half = (c4 & 1) * 8;
            uint32_t addr = ABF + s * 16384 +
                            (uint32_t)(r * 128 + ((cc ^ (r & 7)) << 4) + half);
            asm volatile("st.shared.v2.b32 [%0], {%1,%2};"
                         :: "r"(addr),
                            "r"(*reinterpret_cast<uint32_t*>(&lo)),
                            "r"(*reinterpret_cast<uint32_t*>(&hi)));
        }
    };
    auto compute = [&](int s) {
        uint32_t sA = ABF + s * 16384;
        uint32_t sB = BB + s * 16384;
#pragma unroll
        for (int kk = 0; kk < 4; kk++) {
            uint32_t af[2][4];
#pragma unroll
            for (int mt = 0; mt < 2; mt++) {
                int r = wm * 32 + mt * 16 + (lane & 15);
                int c = kk * 2 + (lane >> 4);
                ldsm_x4(af[mt][0], af[mt][1], af[mt][2], af[mt][3],
                        sA + r * 128 + ((c ^ (r & 7)) << 4));
            }
            uint32_t bf[8][2];
#pragma unroll
            for (int p = 0; p < 4; p++) {
                int r = wn * 64 + p * 16 + ((lane >> 4) << 3) + (lane & 7);
                int c = kk * 2 + ((lane >> 3) & 1);
                ldsm_x4(bf[2 * p][0], bf[2 * p][1], bf[2 * p + 1][0], bf[2 * p + 1][1],
                        sB + r * 128 + ((c ^ (r & 7)) << 4));
            }
#pragma unroll
            for (int mt = 0; mt < 2; mt++)
#pragma unroll
                for (int nt = 0; nt < 8; nt++)
                    mma_bf16(acc[mt][nt], af[mt], bf[nt]);
        }
    };

    // prolog
    load_A_stage(0);
    load_B(0, 0);
    cp_commit();
    cp_wait<0>();
    __syncthreads();
    convert_A(0);
    __syncthreads();

    int s = 0;
#pragma unroll 1
    for (int kc = 0; kc < 4; kc++) {
        if (kc < 3) {
            load_A_stage(kc + 1);
            load_B(s ^ 1, kc + 1);
            cp_commit();
        }
        compute(s);
        if (kc < 3) {
            cp_wait<0>();
            __syncthreads();
            convert_A(s ^ 1);
            __syncthreads();
            s ^= 1;
        }
    }

    const int g = lane >> 2, t4 = lane & 3;
#pragma unroll
    for (int mt = 0; mt < 2; mt++) {
        int r_lo = row0 + wm * 32 + mt * 16 + g;
        int r_hi = r_lo + 8;
        if (dis) {
            float dlo = dis[r_lo], dhi = dis[r_hi];
#pragma unroll
            for (int nt = 0; nt < 8; nt++) {
                int col = col0 + wn * 64 + nt * 8 + 2 * t4;
                __nv_bfloat162 lo = __floats2bfloat162_rn(acc[mt][nt][0] * dlo,
                                                          acc[mt][nt][1] * dlo);
                __nv_bfloat162 hi = __floats2bfloat162_rn(acc[mt][nt][2] * dhi,
                                                          acc[mt][nt][3] * dhi);
                *(__nv_bfloat162*)&Hs[(size_t)r_lo * HDIM + col] = lo;
                *(__nv_bfloat162*)&Hs[(size_t)r_hi * HDIM + col] = hi;
            }
        } else {
#pragma unroll
            for (int nt = 0; nt < 8; nt++) {
                int col = col0 + wn * 64 + nt * 8 + 2 * t4;
                *(float2*)&Cf[(size_t)r_lo * HDIM + col] =
                    make_float2(acc[mt][nt][0], acc[mt][nt][1]);
                *(float2*)&Cf[(size_t)r_hi * HDIM + col] =
                    make_float2(acc[mt][nt][2], acc[mt][nt][3]);
            }
        }
    }
}

// ---------------- CSR gather + fused epilogues ----------------
__global__ __launch_bounds__(256) void k_gather_sub(
    const int* __restrict__ batch, const float* __restrict__ bias)
{
    const int lane = threadIdx.x & 31, grp = threadIdx.x >> 5;
    const uint4* H = (const uint4*)g_hs_sub;
    float4 b0 = ((const float4*)bias)[lane * 2];
    float4 b1 = ((const float4*)bias)[lane * 2 + 1];
#pragma unroll 1
    for (int it = 0; it < 4; it++) {
        int n = blockIdx.x * 32 + it * 8 + grp;
        int o0 = g_off_sub[n] >> 2, o1 = g_off_sub[n + 1] >> 2;
        uint4 a = H[(size_t)n * 32 + lane];
        __nv_bfloat162 A0 = *(__nv_bfloat162*)&a.x, A1 = *(__nv_bfloat162*)&a.y,
                       A2 = *(__nv_bfloat162*)&a.z, A3 = *(__nv_bfloat162*)&a.w;
#pragma unroll 1
        for (int k = o0; k < o1; k++) {
            int4 s4 = ((const int4*)g_csr_sub)[k];
            uint4 v;
            v = H[(size_t)s4.x * 32 + lane];
            A0 = badd2(A0, *(__nv_bfloat162*)&v.x); A1 = badd2(A1, *(__nv_bfloat162*)&v.y);
            A2 = badd2(A2, *(__nv_bfloat162*)&v.z); A3 = badd2(A3, *(__nv_bfloat162*)&v.w);
            v = H[(size_t)s4.y * 32 + lane];
            A0 = badd2(A0, *(__nv_bfloat162*)&v.x); A1 = badd2(A1, *(__nv_bfloat162*)&v.y);
            A2 = badd2(A2, *(__nv_bfloat162*)&v.z); A3 = badd2(A3, *(__nv_bfloat162*)&v.w);
            v = H[(size_t)s4.z * 32 + lane];
            A0 = badd2(A0, *(__nv_bfloat162*)&v.x); A1 = badd2(A1, *(__nv_bfloat162*)&v.y);
            A2 = badd2(A2, *(__nv_bfloat162*)&v.z); A3 = badd2(A3, *(__nv_bfloat162*)&v.w);
            v = H[(size_t)s4.w * 32 + lane];
            A0 = badd2(A0, *(__nv_bfloat162*)&v.x); A1 = badd2(A1, *(__nv_bfloat162*)&v.y);
            A2 = badd2(A2, *(__nv_bfloat162*)&v.z); A3 = badd2(A3, *(__nv_bfloat162*)&v.w);
        }
        float d = g_dis_sub[n];
        float2 f0 = __bfloat1622float2(A0), f1 = __bfloat1622float2(A1);
        float2 f2 = __bfloat1622float2(A2), f3 = __bfloat1622float2(A3);
        float* dst = g_pooled + (size_t)batch[n] * HDIM + lane * 8;
        red4(dst,
             fmaxf(fmaf(f0.x, d, b0.x), 0.0f), fmaxf(fmaf(f0.y, d, b0.y), 0.0f),
             fmaxf(fmaf(f1.x, d, b0.z), 0.0f), fmaxf(fmaf(f1.y, d, b0.w), 0.0f));
        red4(dst + 4,
             fmaxf(fmaf(f2.x, d, b1.x), 0.0f), fmaxf(fmaf(f2.y, d, b1.y), 0.0f),
             fmaxf(fmaf(f3.x, d, b1.z), 0.0f), fmaxf(fmaf(f3.y, d, b1.w), 0.0f));
    }
}

__global__ __launch_bounds__(256) void k_gather_glob(
    const int* __restrict__ batch, const float* __restrict__ bias)
{
    const int lane = threadIdx.x & 31, grp = threadIdx.x >> 5;
    const uint4* H = (const uint4*)g_hs_glob;
    float4 b0 = ((const float4*)bias)[lane * 2];
    float4 b1 = ((const float4*)bias)[lane * 2 + 1];
    float r0 = 0, r1 = 0, r2 = 0, r3 = 0, r4 = 0, r5 = 0, r6 = 0, r7 = 0;
    int cloc = 0;
#pragma unroll 1
    for (int it = 0; it < 4; it++) {
        int n = blockIdx.x * 32 + it * 8 + grp;
        int o0 = g_off_glob[n] >> 2, o1 = g_off_glob[n + 1] >> 2;
        uint4 a = H[(size_t)n * 32 + lane];
        __nv_bfloat162 A0 = *(__nv_bfloat162*)&a.x, A1 = *(__nv_bfloat162*)&a.y,
                       A2 = *(__nv_bfloat162*)&a.z, A3 = *(__nv_bfloat162*)&a.w;
#pragma unroll 1
        for (int k = o0; k < o1; k++) {
            int4 s4 = ((const int4*)g_csr_glob)[k];
            uint4 v;
            v = H[(size_t)s4.x * 32 + lane];
            A0 = badd2(A0, *(__nv_bfloat162*)&v.x); A1 = badd2(A1, *(__nv_bfloat162*)&v.y);
            A2 = badd2(A2, *(__nv_bfloat162*)&v.z); A3 = badd2(A3, *(__nv_bfloat162*)&v.w);
            v = H[(size_t)s4.y * 32 + lane];
            A0 = badd2(A0, *(__nv_bfloat162*)&v.x); A1 = badd2(A1, *(__nv_bfloat162*)&v.y);
            A2 = badd2(A2, *(__nv_bfloat162*)&v.z); A3 = badd2(A3, *(__nv_bfloat162*)&v.w);
            v = H[(size_t)s4.z * 32 + lane];
            A0 = badd2(A0, *(__nv_bfloat162*)&v.x); A1 = badd2(A1, *(__nv_bfloat162*)&v.y);
            A2 = badd2(A2, *(__nv_bfloat162*)&v.z); A3 = badd2(A3, *(__nv_bfloat162*)&v.w);
            v = H[(size_t)s4.w * 32 + lane];
            A0 = badd2(A0, *(__nv_bfloat162*)&v.x); A1 = badd2(A1, *(__nv_bfloat162*)&v.y);
            A2 = badd2(A2, *(__nv_bfloat162*)&v.z); A3 = badd2(A3, *(__nv_bfloat162*)&v.w);
        }
        if (batch[n] == 0) {
            float d = g_dis_glob[n];
            float2 f0 = __bfloat1622float2(A0), f1 = __bfloat1622float2(A1);
            float2 f2 = __bfloat1622float2(A2), f3 = __bfloat1622float2(A3);
            r0 += fmaxf(fmaf(f0.x, d, b0.x), 0.0f);
            r1 += fmaxf(fmaf(f0.y, d, b0.y), 0.0f);
            r2 += fmaxf(fmaf(f1.x, d, b0.z), 0.0f);
            r3 += fmaxf(fmaf(f1.y, d, b0.w), 0.0f);
            r4 += fmaxf(fmaf(f2.x, d, b1.x), 0.0f);
            r5 += fmaxf(fmaf(f2.y, d, b1.y), 0.0f);
            r6 += fmaxf(fmaf(f3.x, d, b1.z), 0.0f);
            r7 += fmaxf(fmaf(f3.y, d, b1.w), 0.0f);
            cloc++;
        }
    }
    float* dst = g_gemb_part + (size_t)(blockIdx.x & 63) * HDIM + lane * 8;
    red4(dst, r0, r1, r2, r3);
    red4(dst + 4, r4, r5, r6, r7);
    if (lane == 0) atomicAdd(&g_gcnt, cloc);
}

// ---------------- misc ----------------
__global__ void k_cnt_sub(const int* __restrict__ batch, int N) {
    int i = blockIdx.x * blockDim.x + threadIdx.x;
    if (i < N) atomicAdd(&g_cnt[batch[i]], 1.0f);
}
__global__ void k_pool_finish() {   // divide pooled in place (fp32)
    int vid = blockIdx.x * blockDim.x + threadIdx.x;   // float4 units over SSEG*64
    if (vid >= SSEG * 64) return;
    int s = vid >> 6;
    float inv = 1.0f / fmaxf(g_cnt[s], 1.0f);
    float4 v = ((const float4*)g_pooled)[vid];
    v.x *= inv; v.y *= inv; v.z *= inv; v.w *= inv;
    ((float4*)g_pooled)[vid] = v;
}
__global__ void k_inject(const int* __restrict__ sub_index) {
    int idx = blockIdx.x * blockDim.x + threadIdx.x;
    if (idx >= SSEG * 128) return;
    int s = idx >> 7, c2 = idx & 127;
    int node = sub_index[s];
    float d = g_dis_glob[node];
    __nv_bfloat162* hp = (__nv_bfloat162*)g_hs_glob + (size_t)node * 128 + c2;
    float2 h = __bfloat1622float2(*hp);
    const float* p = g_p2 + (size_t)s * HDIM + c2 * 2;
    *hp = __floats2bfloat162_rn(fmaf(p[0], d, h.x), fmaf(p[1], d, h.y));
}
__global__ void k_final(const float* __restrict__ fc_W, const float* __restrict__ fc_b,
                        float* __restrict__ out) {
    __shared__ float sg[HDIM];
    int t = threadIdx.x;
    float s = 0.0f;
#pragma unroll 8
    for (int p = 0; p < 64; p++) s += g_gemb_part[p * HDIM + t];
    sg[t] = s / fmaxf((float)g_gcnt, 1.0f);
    __syncthreads();
    float acc = fc_b[t];
    const float* wr = fc_W + (size_t)t * HDIM;
#pragma unroll 8
    for (int h = 0; h < HDIM; h++) acc = fmaf(sg[h], wr[h], acc);
    out[t] = acc;
}

// ---------------- host launcher ----------------
extern "C" void kernel_launch(void* const* d_in, const int* in_sizes, int n_in,
                              void* d_out, int out_size) {
    const float* x_sub      = (const float*)d_in[0];
    const int*   ei_sub     = (const int*)  d_in[1];
    const int*   batch_sub  = (const int*)  d_in[2];
    const int*   sub_index  = (const int*)  d_in[3];
    const float* x_glob     = (const float*)d_in[4];
    const int*   ei_glob    = (const int*)  d_in[5];
    const int*   batch_glob = (const int*)  d_in[6];
    const float* W_sub      = (const float*)d_in[7];
    const float* b_sub      = (const float*)d_in[8];
    const float* W_glob     = (const float*)d_in[9];
    const float* b_glob     = (const float*)d_in[10];
    const float* fc_W       = (const float*)d_in[11];
    const float* fc_b       = (const float*)d_in[12];
    float* out = (float*)d_out;

    const int E_sub  = in_sizes[1] / 2;
    const int E_glob = in_sizes[5] / 2;

    static bool init = false;
    static float *p_dis_sub, *p_dis_glob, *p_pooled, *p_p2;
    static int *p_cd_sub, *p_cd_glob, *p_off_sub, *p_off_glob, *p_cur_sub, *p_cur_glob,
               *p_csr_sub, *p_csr_glob, *p_bs_sub, *p_bs_glob;
    static __nv_bfloat16 *pb_wt_sub, *pb_wt_glob, *p_hs_sub, *p_hs_glob;
    static cudaStream_t s2, s3, s4;
    static cudaEvent_t eStart, eZ, eDs, eDg, ePWg, eCSRs, eCSRg, eG;
    if (!init) {
        init = true;
        cudaGetSymbolAddress((void**)&p_dis_sub,  g_dis_sub);
        cudaGetSymbolAddress((void**)&p_dis_glob, g_dis_glob);
        cudaGetSymbolAddress((void**)&p_pooled,   g_pooled);
        cudaGetSymbolAddress((void**)&p_p2,       g_p2);
        cudaGetSymbolAddress((void**)&p_cd_sub,   g_cntdeg_sub);
        cudaGetSymbolAddress((void**)&p_cd_glob,  g_cntdeg_glob);
        cudaGetSymbolAddress((void**)&p_off_sub,  g_off_sub);
        cudaGetSymbolAddress((void**)&p_off_glob, g_off_glob);
        cudaGetSymbolAddress((void**)&p_cur_sub,  g_cur_sub);
        cudaGetSymbolAddress((void**)&p_cur_glob, g_cur_glob);
        cudaGetSymbolAddress((void**)&p_csr_sub,  g_csr_sub);
        cudaGetSymbolAddress((void**)&p_csr_glob, g_csr_glob);
        cudaGetSymbolAddress((void**)&p_bs_sub,   g_bsum_sub);
        cudaGetSymbolAddress((void**)&p_bs_glob,  g_bsum_glob);
        cudaGetSymbolAddress((void**)&pb_wt_sub,  g_bWt_sub);
        cudaGetSymbolAddress((void**)&pb_wt_glob, g_bWt_glob);
        cudaGetSymbolAddress((void**)&p_hs_sub,   g_hs_sub);
        cudaGetSymbolAddress((void**)&p_hs_glob,  g_hs_glob);
        cudaFuncSetAttribute(k_gemm_mma, cudaFuncAttributeMaxDynamicSharedMemorySize, GEMM_SMEM);
        cudaStreamCreateWithFlags(&s2, cudaStreamNonBlocking);
        cudaStreamCreateWithFlags(&s3, cudaStreamNonBlocking);
        cudaStreamCreateWithFlags(&s4, cudaStreamNonBlocking);
        cudaEventCreateWithFlags(&eStart, cudaEventDisableTiming);
        cudaEventCreateWithFlags(&eZ,     cudaEventDisableTiming);
        cudaEventCreateWithFlags(&eDs,    cudaEventDisableTiming);
        cudaEventCreateWithFlags(&eDg,    cudaEventDisableTiming);
        cudaEventCreateWithFlags(&ePWg,   cudaEventDisableTiming);
        cudaEventCreateWithFlags(&eCSRs,  cudaEventDisableTiming);
        cudaEventCreateWithFlags(&eCSRg,  cudaEventDisableTiming);
        cudaEventCreateWithFlags(&eG,     cudaEventDisableTiming);
    }

    // ---- fork ----
    cudaEventRecord(eStart, 0);
    cudaStreamWaitEvent(s2, eStart, 0);
    cudaStreamWaitEvent(s3, eStart, 0);
    cudaStreamWaitEvent(s4, eStart, 0);

    // s0: zeroing
    k_zero_cnt <<<NGLOB / 256, 256>>>();
    cudaEventRecord(eZ, 0);
    k_zero_rest<<<(SSEG * HDIM + 255) / 256, 256>>>();

    // ---- s2: glob CSR build ----
    cudaStreamWaitEvent(s2, eZ, 0);
    k_hist <<<(E_glob + 255) / 256, 256, 0, s2>>>(p_cd_glob, ei_glob, E_glob);
    k_scan1<<<NGLOB / 256, 256, 0, s2>>>(p_cd_glob, p_dis_glob, p_bs_glob);
    cudaEventRecord(eDg, s2);
    k_scan2<<<1, 256, 0, s2>>>(p_bs_glob, NGLOB / 256);
    k_scan3<<<NGLOB / 256, 256, 0, s2>>>(p_cd_glob, p_bs_glob, p_off_glob, p_cur_glob, NGLOB);
    k_fill <<<(E_glob + 255) / 256, 256, 0, s2>>>(p_csr_glob, p_cur_glob, ei_glob, E_glob);
    k_pad  <<<NGLOB / 256, 256, 0, s2>>>(p_cd_glob, p_off_glob, p_csr_glob, NGLOB);
    cudaEventRecord(eCSRg, s2);

    // ---- s3: glob W pack + GEMM (fp32 A direct) ----
    k_pack_Wt<<<dim3(8, 8), 256, 0, s3>>>(W_glob, pb_wt_glob);
    cudaEventRecord(ePWg, s3);
    cudaStreamWaitEvent(s3, eDg, 0);
    k_gemm_mma<<<dim3(NGLOB / 128, 2), 256, GEMM_SMEM, s3>>>(x_glob, pb_wt_glob,
                                                             p_hs_glob, nullptr, p_dis_glob);
    cudaEventRecord(eG, s3);

    // ---- s4: sub CSR build ----
    cudaStreamWaitEvent(s4, eZ, 0);
    k_hist <<<(E_sub + 255) / 256, 256, 0, s4>>>(p_cd_sub, ei_sub, E_sub);
    k_scan1<<<NSUB / 256, 256, 0, s4>>>(p_cd_sub, p_dis_sub, p_bs_sub);
    cudaEventRecord(eDs, s4);
    k_scan2<<<1, 256, 0, s4>>>(p_bs_sub, NSUB / 256);
    k_scan3<<<NSUB / 256, 256, 0, s4>>>(p_cd_sub, p_bs_sub, p_off_sub, p_cur_sub, NSUB);
    k_fill <<<(E_sub + 255) / 256, 256, 0, s4>>>(p_csr_sub, p_cur_sub, ei_sub, E_sub);
    k_pad  <<<NSUB / 256, 256, 0, s4>>>(p_cd_sub, p_off_sub, p_csr_sub, NSUB);
    cudaEventRecord(eCSRs, s4);

    // ---- s0: sub GEMM/gather + pooled GEMM + join tail ----
    k_pack_Wt<<<dim3(8, 8), 256>>>(W_sub, pb_wt_sub);
    k_cnt_sub<<<(NSUB + 255) / 256, 256>>>(batch_sub, NSUB);
    cudaStreamWaitEvent(0, eDs, 0);
    k_gemm_mma<<<dim3(NSUB / 128, 2), 256, GEMM_SMEM>>>(x_sub, pb_wt_sub,
                                                        p_hs_sub, nullptr, p_dis_sub);
    cudaStreamWaitEvent(0, eCSRs, 0);
    k_gather_sub<<<NSUB / 32, 256>>>(batch_sub, b_sub);
    k_pool_finish<<<(SSEG * 64 + 255) / 256, 256>>>();
    cudaStreamWaitEvent(0, ePWg, 0);
    k_gemm_mma<<<dim3(SSEG / 128, 2), 256, GEMM_SMEM>>>(p_pooled, pb_wt_glob,
                                                        nullptr, p_p2, nullptr);

    cudaStreamWaitEvent(0, eG, 0);
    k_inject<<<(SSEG * 128 + 255) / 256, 256>>>(sub_index);
    cudaStreamWaitEvent(0, eCSRg, 0);
    k_gather_glob<<<NGLOB / 32, 256>>>(batch_glob, b_glob);
    k_final<<<1, 256>>>(fc_W, fc_b, out);
}